// round 17
// baseline (speedup 1.0000x reference)
#include <cuda_runtime.h>
#include <cuda_bf16.h>
#include <cuda_fp16.h>
#include <math.h>
#include <stdint.h>

#define BATCH 4
#define SL    1024
#define DM    768
#define NH    12
#define FF    3072
#define NVOC  50257
#define NVP   50432
#define MT    (BATCH*SL)
#define NLAY  2

#define S_C   512
#define S_C2  256
#define S_Q   128
#define S_R   128

#define GF_RESID 1
#define GF_GELU  2
#define GF_WPE   4
#define GF_QKV   8

typedef __nv_bfloat16 bf16;

// ---------------- scratch ---------------------------------------------------
__device__ float g_h[MT*DM];

__device__ bf16 g_xh[MT*DM], g_xl[MT*DM];
__device__ bf16 g_lwh[DM*DM], g_lwl[DM*DM];

__device__ __half g_x16[MT*DM];
__device__ __half g_a16[MT*DM];
__device__ __half g_f16[(size_t)MT*FF];
__device__ __half g_wtf[(size_t)NVP*DM];
__device__ __half g_qw16[NLAY*3*DM*DM];
__device__ __half g_ow16[NLAY*DM*DM];
__device__ __half g_fw16[NLAY*FF*DM];
__device__ __half g_pw16[NLAY*DM*FF];
__device__ __half g_q16[(size_t)BATCH*NH*SL*64];
__device__ __half g_k16[(size_t)BATCH*NH*SL*64];
__device__ __half g_vt [(size_t)BATCH*NH*64*SL];

// ---------------- asm helpers -----------------------------------------------
__device__ __forceinline__ uint32_t smem_u32(const void* p){
    uint32_t a;
    asm("{ .reg .u64 t; cvta.to.shared.u64 t, %1; cvt.u32.u64 %0, t; }" : "=r"(a) : "l"(p));
    return a;
}
__device__ __forceinline__ void cpa16(uint32_t d, const void* s){
    asm volatile("cp.async.cg.shared.global [%0], [%1], 16;" :: "r"(d), "l"(s));
}
#define CP_COMMIT() asm volatile("cp.async.commit_group;" ::: "memory")
#define CP_WAIT(n)  asm volatile("cp.async.wait_group %0;" :: "n"(n) : "memory")

#define LDSM4(r0,r1,r2,r3,a) \
    asm volatile("ldmatrix.sync.aligned.m8n8.x4.shared.b16 {%0,%1,%2,%3}, [%4];" \
        : "=r"(r0),"=r"(r1),"=r"(r2),"=r"(r3) : "r"(a))

#define MMA16816(d, a, b0, b1) \
    asm volatile("mma.sync.aligned.m16n8k16.row.col.f32.bf16.bf16.f32 " \
        "{%0,%1,%2,%3},{%4,%5,%6,%7},{%8,%9},{%0,%1,%2,%3};" \
        : "+f"((d)[0]),"+f"((d)[1]),"+f"((d)[2]),"+f"((d)[3]) \
        : "r"((a)[0]),"r"((a)[1]),"r"((a)[2]),"r"((a)[3]),"r"(b0),"r"(b1))

#define MMA16816H(d, a, b0, b1) \
    asm volatile("mma.sync.aligned.m16n8k16.row.col.f32.f16.f16.f32 " \
        "{%0,%1,%2,%3},{%4,%5,%6,%7},{%8,%9},{%0,%1,%2,%3};" \
        : "+f"((d)[0]),"+f"((d)[1]),"+f"((d)[2]),"+f"((d)[3]) \
        : "r"((a)[0]),"r"((a)[1]),"r"((a)[2]),"r"((a)[3]),"r"(b0),"r"(b1))

__device__ __forceinline__ uint32_t pack_h2(float a, float b){
    __half2 h = __floats2half2_rn(a, b);
    return *(uint32_t*)&h;
}

// ---------------- fused token build + embedding gather -----------------------
__global__ void __launch_bounds__(192)
k_embed(const float* __restrict__ wte,
        const int* __restrict__ ctx, const int* __restrict__ qry,
        const int* __restrict__ rsp, const int* __restrict__ c2,
        const int* __restrict__ cl, const int* __restrict__ ql,
        const int* __restrict__ rl, const int* __restrict__ c2l)
{
    int row = blockIdx.x;
    int c4 = threadIdx.x;           // 0..191 (DM/4)
    int b = row >> 10, p = row & (SL-1);
    int l0 = cl[b], l1 = c2l[b], l2 = ql[b], l3 = rl[b];
    int tok = -1;
    if (p < l0)               tok = ctx[b*S_C + p];
    else if (p < l0+l1)       tok = c2 [b*S_C2 + (p-l0)];
    else if (p < l0+l1+l2)    tok = qry[b*S_Q + (p-l0-l1)];
    else if (p < l0+l1+l2+l3) tok = rsp[b*S_R + (p-l0-l1-l2)];

    float4 v = make_float4(0.f,0.f,0.f,0.f);
    if (tok >= 0) v = ((const float4*)(wte + (size_t)tok*DM))[c4];
    float vv[4] = {v.x, v.y, v.z, v.w};
    size_t o = (size_t)row*DM + c4*4;
    #pragma unroll
    for (int t=0;t<4;t++){
        bf16 h = __float2bfloat16(vv[t]);
        g_xh[o+t] = h;
        g_xl[o+t] = __float2bfloat16(vv[t] - __bfloat162float(h));
    }
}

// ---------------- conversions ------------------------------------------------
__global__ void k_cvt_f16(const float* __restrict__ in, __half* __restrict__ o,
                          int nin, int ntot)
{
    int i = blockIdx.x*blockDim.x + threadIdx.x;
    if (i >= ntot) return;
    float v = (i < nin) ? in[i] : 0.f;
    o[i] = __float2half(v);
}

__global__ void k_cvt(const float* __restrict__ in, bf16* __restrict__ oh,
                      bf16* __restrict__ ol, int nin, int ntot)
{
    int i = blockIdx.x*blockDim.x + threadIdx.x;
    if (i >= ntot) return;
    float v = (i < nin) ? in[i] : 0.f;
    bf16 h = __float2bfloat16(v);
    oh[i] = h;
    ol[i] = __float2bfloat16(v - __bfloat162float(h));
}

// fused transpose+fp16 conversion for all 8 layer weight matrices.
__global__ void k_cvtT_all(const float* __restrict__ wqkv, const float* __restrict__ wo,
                           const float* __restrict__ wfc,  const float* __restrict__ wpr)
{
    __shared__ float t[32][33];
    const int off[9] = {0,1728,2304,4608,6912,8640,9216,11520,13824};
    int bid = blockIdx.x;
    int s = 0;
    #pragma unroll
    for (int i = 1; i < 8; i++)
        if (bid >= off[i]) s = i;
    int start = off[s];
    int l = s >> 2, m = s & 3;
    int Kd, Nd;
    const float* src;
    __half* dst;
    if (m == 0)      { Kd = DM;  Nd = 3*DM; src = wqkv + (size_t)l*DM*3*DM; dst = g_qw16 + (size_t)l*3*DM*DM; }
    else if (m == 1) { Kd = DM;  Nd = DM;   src = wo   + (size_t)l*DM*DM;   dst = g_ow16 + (size_t)l*DM*DM; }
    else if (m == 2) { Kd = DM;  Nd = FF;   src = wfc  + (size_t)l*DM*FF;   dst = g_fw16 + (size_t)l*FF*DM; }
    else             { Kd = FF;  Nd = DM;   src = wpr  + (size_t)l*FF*DM;   dst = g_pw16 + (size_t)l*DM*FF; }
    int tloc = bid - start;
    int tilesX = Nd >> 5;
    int nb = (tloc % tilesX) * 32;
    int kb = (tloc / tilesX) * 32;
    int tx = threadIdx.x, ty = threadIdx.y;
    #pragma unroll
    for (int i=0;i<32;i+=8)
        t[ty+i][tx] = src[(size_t)(kb+ty+i)*Nd + nb+tx];
    __syncthreads();
    #pragma unroll
    for (int i=0;i<32;i+=8)
        dst[(size_t)(nb+ty+i)*Kd + kb+tx] = __float2half(t[tx][ty+i]);
}

// LayerNorm fp32 -> fp16
__global__ void __launch_bounds__(256)
k_ln_f16(const float* __restrict__ in, const float* __restrict__ gm,
         const float* __restrict__ bt, __half* __restrict__ o16)
{
    __shared__ float red[256];
    int row = blockIdx.x, tid = threadIdx.x;
    const float* x = in + (size_t)row*DM;
    float v0 = x[tid], v1 = x[tid+256], v2 = x[tid+512];
    red[tid] = v0+v1+v2; __syncthreads();
    for (int o=128;o>0;o>>=1){ if(tid<o) red[tid]+=red[tid+o]; __syncthreads(); }
    float mean = red[0] * (1.f/768.f); __syncthreads();
    float d0=v0-mean, d1=v1-mean, d2=v2-mean;
    red[tid] = d0*d0+d1*d1+d2*d2; __syncthreads();
    for (int o=128;o>0;o>>=1){ if(tid<o) red[tid]+=red[tid+o]; __syncthreads(); }
    float inv = rsqrtf(red[0]*(1.f/768.f) + 1e-5f);
    #pragma unroll
    for (int t=0;t<3;t++){
        int c = tid + t*256;
        float d = (t==0)?d0:((t==1)?d1:d2);
        o16[(size_t)row*DM + c] = __float2half(d*inv*gm[c] + bt[c]);
    }
}

// ---------------- fused flash attention --------------------------------------
__global__ void __launch_bounds__(256,1)
k_flash(const int* __restrict__ cl, const int* __restrict__ c2l,
        const int* __restrict__ ql, const int* __restrict__ rl)
{
    __shared__ __align__(128) unsigned char smem_buf[49152];
    uint32_t sb = smem_u32(smem_buf);
    int tid = threadIdx.x, w = tid>>5, lane = tid&31;
    int bh = blockIdx.y, b = bh / NH, hh = bh % NH;
    int q0 = blockIdx.x * 128;
    int total = cl[b] + c2l[b] + ql[b] + rl[b];

    const __half* Qb = g_q16 + (size_t)bh*SL*64;
    const __half* Kb = g_k16 + (size_t)bh*SL*64;
    const __half* Vb = g_vt  + (size_t)bh*64*SL;

    for (int u = tid; u < 1024; u += 256) {
        int r = u>>3, c = u&7;
        cpa16(sb + r*128 + ((c^(r&7))*16), Qb + (size_t)(q0+r)*64 + c*8);
    }
    for (int u = tid; u < 512; u += 256) {
        int r = u>>3, c = u&7;
        uint32_t d = r*128 + ((c^(r&7))*16);
        cpa16(sb + 16384 + d,        Kb + (size_t)r*64 + c*8);
        cpa16(sb + 16384 + 8192 + d, Vb + (size_t)r*SL + c*8);
    }
    CP_COMMIT();
    CP_WAIT(0);
    __syncthreads();

    int rr = lane & 15, hf = lane >> 4;

    uint32_t qf[4][4];
    #pragma unroll
    for (int ks=0; ks<4; ks++) {
        int r = w*16 + rr;
        int ch = ks*2 + hf;
        LDSM4(qf[ks][0],qf[ks][1],qf[ks][2],qf[ks][3], sb + r*128 + ((ch^(r&7))*16));
    }

    float Oacc[8][4];
    #pragma unroll
    for (int nd=0;nd<8;nd++)
        #pragma unroll
        for (int j=0;j<4;j++) Oacc[nd][j]=0.f;
    float mrow[2] = {-1e30f,-1e30f}, lrow[2] = {0.f,0.f};
    int qi0 = q0 + w*16 + (lane>>2);

    int nk = q0/64 + 2;
    int nkt = (total + 63) >> 6;
    if (nkt < nk) nk = nkt;

    for (int i = 0; i < nk; i++) {
        uint32_t st = sb + 16384 + (i&1)*16384;
        if (i+1 < nk) {
            uint32_t st2 = sb + 16384 + ((i+1)&1)*16384;
            int k0n = (i+1)*64;
            for (int u = tid; u < 512; u += 256) {
                int r = u>>3, c = u&7;
                uint32_t d = r*128 + ((c^(r&7))*16);
                cpa16(st2 + d,        Kb + (size_t)(k0n+r)*64 + c*8);
                cpa16(st2 + 8192 + d, Vb + (size_t)r*SL + k0n + c*8);
            }
            CP_COMMIT();
            CP_WAIT(1);
        } else {
            CP_WAIT(0);
        }
        __syncthreads();

        int k0 = i*64;
        float Sacc[8][4];
        #pragma unroll
        for (int n8=0;n8<8;n8++)
            #pragma unroll
            for (int j=0;j<4;j++) Sacc[n8][j]=0.f;
        #pragma unroll
        for (int ks=0; ks<4; ks++) {
            uint32_t bf[4][4];
            int ch = ks*2 + hf;
            #pragma unroll
            for (int nt=0; nt<4; nt++) {
                int r = nt*16 + rr;
                LDSM4(bf[nt][0],bf[nt][1],bf[nt][2],bf[nt][3], st + r*128 + ((ch^(r&7))*16));
            }
            #pragma unroll
            for (int nt=0; nt<4; nt++) {
                MMA16816H(Sacc[nt*2+0], qf[ks], bf[nt][0], bf[nt][2]);
                MMA16816H(Sacc[nt*2+1], qf[ks], bf[nt][1], bf[nt][3]);
            }
        }
        #pragma unroll
        for (int n8=0;n8<8;n8++)
            #pragma unroll
            for (int j=0;j<4;j++) {
                int kk = k0 + n8*8 + (lane&3)*2 + (j&1);
                int qi = qi0 + (j>>1)*8;
                float v = Sacc[n8][j]*0.125f;
                Sacc[n8][j] = (kk<=qi && kk<total) ? v : -1e30f;
            }
        float cm[2] = {-1e30f,-1e30f};
        #pragma unroll
        for (int n8=0;n8<8;n8++) {
            cm[0] = fmaxf(cm[0], fmaxf(Sacc[n8][0], Sacc[n8][1]));
            cm[1] = fmaxf(cm[1], fmaxf(Sacc[n8][2], Sacc[n8][3]));
        }
        #pragma unroll
        for (int o=1;o<4;o<<=1) {
            cm[0] = fmaxf(cm[0], __shfl_xor_sync(0xffffffffu, cm[0], o));
            cm[1] = fmaxf(cm[1], __shfl_xor_sync(0xffffffffu, cm[1], o));
        }
        float mnew[2], corr[2];
        #pragma unroll
        for (int h=0;h<2;h++) {
            mnew[h] = fmaxf(mrow[h], cm[h]);
            corr[h] = __expf(mrow[h] - mnew[h]);
        }
        float ls[2] = {0.f,0.f};
        #pragma unroll
        for (int n8=0;n8<8;n8++)
            #pragma unroll
            for (int j=0;j<4;j++) {
                float p = __expf(Sacc[n8][j] - mnew[j>>1]);
                Sacc[n8][j] = p;
                ls[j>>1] += p;
            }
        #pragma unroll
        for (int o=1;o<4;o<<=1) {
            ls[0] += __shfl_xor_sync(0xffffffffu, ls[0], o);
            ls[1] += __shfl_xor_sync(0xffffffffu, ls[1], o);
        }
        #pragma unroll
        for (int h=0;h<2;h++) {
            lrow[h] = lrow[h]*corr[h] + ls[h];
            mrow[h] = mnew[h];
        }
        #pragma unroll
        for (int nd=0;nd<8;nd++) {
            Oacc[nd][0] *= corr[0]; Oacc[nd][1] *= corr[0];
            Oacc[nd][2] *= corr[1]; Oacc[nd][3] *= corr[1];
        }
        #pragma unroll
        for (int kf=0; kf<4; kf++) {
            uint32_t ph[4];
            ph[0] = pack_h2(Sacc[2*kf  ][0], Sacc[2*kf  ][1]);
            ph[1] = pack_h2(Sacc[2*kf  ][2], Sacc[2*kf  ][3]);
            ph[2] = pack_h2(Sacc[2*kf+1][0], Sacc[2*kf+1][1]);
            ph[3] = pack_h2(Sacc[2*kf+1][2], Sacc[2*kf+1][3]);
            uint32_t bv[4][4];
            int ch = kf*2 + hf;
            #pragma unroll
            for (int nt=0; nt<4; nt++) {
                int r = nt*16 + rr;
                LDSM4(bv[nt][0],bv[nt][1],bv[nt][2],bv[nt][3], st + 8192 + r*128 + ((ch^(r&7))*16));
            }
            #pragma unroll
            for (int nt=0; nt<4; nt++) {
                MMA16816H(Oacc[nt*2+0], ph, bv[nt][0], bv[nt][2]);
                MMA16816H(Oacc[nt*2+1], ph, bv[nt][1], bv[nt][3]);
            }
        }
        __syncthreads();
    }

    float inv0 = 1.f/lrow[0], inv1 = 1.f/lrow[1];
    #pragma unroll
    for (int nd=0; nd<8; nd++)
        #pragma unroll
        for (int h=0; h<2; h++) {
            int s = qi0 + h*8;
            int d = nd*8 + (lane&3)*2;
            float inv = h ? inv1 : inv0;
            size_t o = (size_t)(b*SL + s)*DM + hh*64 + d;
            *(__half2*)(g_a16 + o) =
                __floats2half2_rn(Oacc[nd][h*2+0]*inv, Oacc[nd][h*2+1]*inv);
        }
}

// ---------------- split-bf16 GEMM (ll only) ----------------------------------
#define KC 64
#define AB (128*128)

template<int BN>
__global__ void __launch_bounds__(256,1)
k_tgemm(const bf16* __restrict__ aH, const bf16* __restrict__ aL,
        const bf16* __restrict__ bH, const bf16* __restrict__ bL,
        const float* __restrict__ bias, const float* __restrict__ wpe,
        float* __restrict__ C, int K, int Nvalid, int flags)
{
    constexpr int WN  = BN/4;
    constexpr int NT  = WN/16;
    constexpr int N8  = WN/8;
    constexpr int BB  = BN*128;
    constexpr int STG = 2*AB + 2*BB;

    extern __shared__ __align__(128) unsigned char smem_buf[];
    uint32_t sb = smem_u32(smem_buf);
    int tid = threadIdx.x;
    int bm = blockIdx.x * 128;
    int bn = blockIdx.y * BN;

    int w = tid >> 5, lane = tid & 31;
    int wm = w >> 2, wn = w & 3;

    float acc[4][N8][4];
    #pragma unroll
    for (int mt=0;mt<4;mt++)
        #pragma unroll
        for (int n8=0;n8<N8;n8++)
            #pragma unroll
            for (int r=0;r<4;r++) acc[mt][n8][r]=0.f;

    int nk = K / KC;

    auto load_stage = [&](int stage, int k0){
        uint32_t st = sb + stage*STG;
        #pragma unroll 4
        for (int u = tid; u < 128*8; u += 256) {
            int r = u >> 3, c = u & 7;
            uint32_t d = r*128 + ((c ^ (r&7))*16);
            size_t g = (size_t)(bm+r)*K + k0 + c*8;
            cpa16(st + d,      aH + g);
            cpa16(st + AB + d, aL + g);
        }
        #pragma unroll 4
        for (int u = tid; u < BN*8; u += 256) {
            int r = u >> 3, c = u & 7;
            uint32_t d = r*128 + ((c ^ (r&7))*16);
            size_t g = (size_t)(bn+r)*K + k0 + c*8;
            cpa16(st + 2*AB + d,      bH + g);
            cpa16(st + 2*AB + BB + d, bL + g);
        }
        CP_COMMIT();
    };

    load_stage(0, 0);

    int rr = lane & 15, hf = lane >> 4;
    for (int i = 0; i < nk; i++) {
        uint32_t st = sb + (i & 1)*STG;
        if (i + 1 < nk) { load_stage((i+1)&1, (i+1)*KC); CP_WAIT(1); }
        else            { CP_WAIT(0); }
        __syncthreads();

        #pragma unroll
        for (int ks = 0; ks < 4; ks++) {
            uint32_t ah[4][4], al[4][4], bh[NT][4], bl[NT][4];
            int ch = ks*2 + hf;
            #pragma unroll
            for (int mt=0;mt<4;mt++) {
                int r = wm*64 + mt*16 + rr;
                uint32_t ra = st + r*128 + ((ch ^ (r&7))*16);
                LDSM4(ah[mt][0],ah[mt][1],ah[mt][2],ah[mt][3], ra);
                LDSM4(al[mt][0],al[mt][1],al[mt][2],al[mt][3], ra + AB);
            }
            #pragma unroll
            for (int nt=0;nt<NT;nt++) {
                int r = wn*WN + nt*16 + rr;
                uint32_t rb = st + 2*AB + r*128 + ((ch ^ (r&7))*16);
                LDSM4(bh[nt][0],bh[nt][1],bh[nt][2],bh[nt][3], rb);
                LDSM4(bl[nt][0],bl[nt][1],bl[nt][2],bl[nt][3], rb + BB);
            }
            #pragma unroll
            for (int mt=0;mt<4;mt++) {
                #pragma unroll
                for (int n8=0;n8<N8;n8++) {
                    int nt = n8 >> 1, p = n8 & 1;
                    MMA16816(acc[mt][n8], ah[mt], bh[nt][p], bh[nt][p+2]);
                    MMA16816(acc[mt][n8], ah[mt], bl[nt][p], bl[nt][p+2]);
                    MMA16816(acc[mt][n8], al[mt], bh[nt][p], bh[nt][p+2]);
                }
            }
        }
        __syncthreads();
    }

    int r0b = bm + wm*64 + (lane >> 2);
    int c0b = bn + wn*WN + (lane & 3)*2;
    #pragma unroll
    for (int mt=0;mt<4;mt++) {
        #pragma unroll
        for (int n8=0;n8<N8;n8++) {
            #pragma unroll
            for (int half=0; half<2; half++) {
                int r = r0b + mt*16 + half*8;
                int c = c0b + n8*8;
                float v0 = acc[mt][n8][half*2+0];
                float v1 = acc[mt][n8][half*2+1];
                if (bias) { v0 += bias[c]; v1 += bias[c+1]; }
                if (flags & GF_WPE) {
                    const float* wp = wpe + (size_t)(r & (SL-1))*DM + c;
                    v0 += wp[0]; v1 += wp[1];
                }
                size_t o = (size_t)r*Nvalid + c;
                if (flags & GF_RESID) {
                    float2 old = *(float2*)(C + o);
                    old.x += v0; old.y += v1;
                    *(float2*)(C + o) = old;
                } else {
                    C[o] = v0; C[o+1] = v1;
                }
            }
        }
    }
}

#define SMEM128 (2*(2*AB + 2*128*128))   /* 131072 */

// ---------------- fp16 single-pass GEMM, 512 threads -------------------------
template<int BN>
__global__ void __launch_bounds__(512,1)
k_hgemm(const __half* __restrict__ Af, const __half* __restrict__ Bf,
        const float* __restrict__ bias,
        float* __restrict__ C, __half* __restrict__ C16,
        int K, int Nvalid, int flags)
{
    constexpr int WN = BN/4;
    constexpr int NT = WN/16;
    constexpr int N8 = WN/8;
    constexpr int HA = 16384;
    constexpr int HB = BN*128;
    constexpr int ST = HA+HB;

    extern __shared__ __align__(128) unsigned char smem_buf[];
    uint32_t sb = smem_u32(smem_buf);
    int tid = threadIdx.x;
    int bm = blockIdx.x * 128;
    int bn = blockIdx.y * BN;

    int w = tid >> 5, lane = tid & 31;
    int wm = w >> 2, wn = w & 3;

    float acc[2][N8][4];
    #pragma unroll
    for (int mt=0;mt<2;mt++)
        #pragma unroll
        for (int n8=0;n8<N8;n8++)
            #pragma unroll
            for (int r=0;r<4;r++) acc[mt][n8][r]=0.f;

    int nk = K / KC;

    auto load_stage = [&](int stage, int k0){
        uint32_t st = sb + stage*ST;
        #pragma unroll 2
        for (int u = tid; u < 128*8; u += 512) {
            int r = u >> 3, c = u & 7;
            uint32_t d = r*128 + ((c ^ (r&7))*16);
            cpa16(st + d, Af + (size_t)(bm+r)*K + k0 + c*8);
        }
        #pragma unroll 4
        for (int u = tid; u < BN*8; u += 512) {
            int r = u >> 3, c = u & 7;
            uint32_t d = r*128 + ((c ^ (r&7))*16);
            cpa16(st + HA + d, Bf + (size_t)(bn+r)*K + k0 + c*8);
        }
        CP_COMMIT();
    };

    load_stage(0, 0);
    if (nk > 1) load_stage(1, KC);

    int rr = lane & 15, hf = lane >> 4;
    int stage = 0;
    for (int i = 0; i < nk; i++) {
        if (i + 2 < nk) { load_stage((stage+2)%3, (i+2)*KC); CP_WAIT(2); }
        else if (i + 1 < nk) { CP_WAIT(1); }
        else { CP_WAIT(0); }
        __syncthreads();

        uint32_t st = sb + stage*ST;
        #pragma unroll
        for (int ks = 0; ks < 4; ks++) {
            uint32_t ah[2][4], bh[NT][4];
            int ch = ks*2 + hf;
            #pragma unroll
            for (int mt=0;mt<2;mt++) {
                int r = wm*32 + mt*16 + rr;
                LDSM4(ah[mt][0],ah[mt][1],ah[mt][2],ah[mt][3], st + r*128 + ((ch ^ (r&7))*16));
            }
            #pragma unroll
            for (int nt=0;nt<NT;nt++) {
                int r = wn*WN + nt*16 + rr;
                LDSM4(bh[nt][0],bh[nt][1],bh[nt][2],bh[nt][3], st + HA + r*128 + ((ch ^ (r&7))*16));
            }
            #pragma unroll
            for (int mt=0;mt<2;mt++) {
                #pragma unroll
                for (int n8=0;n8<N8;n8++) {
                    int nt = n8 >> 1, p = n8 & 1;
                    MMA16816H(acc[mt][n8], ah[mt], bh[nt][p], bh[nt][p+2]);
                }
            }
        }
        __syncthreads();
        stage = (stage + 1) % 3;
    }

    int r0b = bm + wm*32 + (lane >> 2);
    int c0b = bn + wn*WN + (lane & 3)*2;
    #pragma unroll
    for (int mt=0;mt<2;mt++) {
        #pragma unroll
        for (int n8=0;n8<N8;n8++) {
            #pragma unroll
            for (int half=0; half<2; half++) {
                int r = r0b + mt*16 + half*8;
                int c = c0b + n8*8;
                float v0 = acc[mt][n8][half*2+0];
                float v1 = acc[mt][n8][half*2+1];
                if (bias) { v0 += bias[c]; v1 += bias[c+1]; }
                if (flags & GF_QKV) {
                    int sec = c / DM;
                    int cc = c - sec*DM;
                    int hh = cc >> 6, d = cc & 63;
                    int bb2 = r >> 10, s = r & (SL-1);
                    if (sec < 2) {
                        __half* dst = (sec == 0 ? g_q16 : g_k16)
                                      + (((size_t)(bb2*NH + hh)*SL + s) << 6) + d;
                        *(__half2*)dst = __floats2half2_rn(v0, v1);
                    } else {
                        __half* dst = g_vt + ((size_t)(bb2*NH + hh)*64 + d)*SL + s;
                        dst[0]  = __float2half(v0);
                        dst[SL] = __float2half(v1);
                    }
                    continue;
                }
                if (flags & GF_GELU) {
                    float u0=v0, u1=v1;
                    v0 = 0.5f*u0*(1.f + tanhf(0.7978845608028654f*(u0 + 0.044715f*u0*u0*u0)));
                    v1 = 0.5f*u1*(1.f + tanhf(0.7978845608028654f*(u1 + 0.044715f*u1*u1*u1)));
                    *(__half2*)(C16 + (size_t)r*Nvalid + c) = __floats2half2_rn(v0, v1);
                    continue;
                }
                size_t o = (size_t)r*Nvalid + c;
                if (flags & GF_RESID) {
                    float2 old = *(float2*)(C + o);
                    old.x += v0; old.y += v1;
                    *(float2*)(C + o) = old;
                } else {
                    if (c < Nvalid)   C[o]   = v0;
                    if (c+1 < Nvalid) C[o+1] = v1;
                }
            }
        }
    }
}

#define SMEMH256 (3*(16384 + 256*128))   /* 147456 */
#define SMEMH128 (3*(16384 + 128*128))   /* 98304 */

// ---------------- launch ----------------------------------------------------
extern "C" void kernel_launch(void* const* d_in, const int* in_sizes, int n_in,
                              void* d_out, int out_size)
{
    const int*   ctx  = (const int*)  d_in[0];
    const int*   qry  = (const int*)  d_in[1];
    const int*   rsp  = (const int*)  d_in[2];
    const int*   c2   = (const int*)  d_in[3];
    const int*   cl   = (const int*)  d_in[4];
    const int*   ql   = (const int*)  d_in[5];
    const int*   rl   = (const int*)  d_in[6];
    const int*   c2l  = (const int*)  d_in[7];
    const float* wte  = (const float*)d_in[8];
    const float* wpe  = (const float*)d_in[9];
    const float* ln1g = (const float*)d_in[10];
    const float* ln1b = (const float*)d_in[11];
    const float* wqkv = (const float*)d_in[12];
    const float* bqkv = (const float*)d_in[13];
    const float* wo   = (const float*)d_in[14];
    const float* bo   = (const float*)d_in[15];
    const float* ln2g = (const float*)d_in[16];
    const float* ln2b = (const float*)d_in[17];
    const float* wfc  = (const float*)d_in[18];
    const float* bfc  = (const float*)d_in[19];
    const float* wpr  = (const float*)d_in[20];
    const float* bpr  = (const float*)d_in[21];
    const float* lnfg = (const float*)d_in[22];
    const float* lnfb = (const float*)d_in[23];
    const float* llw  = (const float*)d_in[24];
    const float* llb  = (const float*)d_in[25];
    float* out = (float*)d_out;

    static int inited = 0;
    static cudaStream_t s2;
    static cudaEvent_t ev_fork, ev_cvtT, ev_wtf;
    if (!inited) {
        cudaFuncSetAttribute(k_tgemm<128>, cudaFuncAttributeMaxDynamicSharedMemorySize, SMEM128);
        cudaFuncSetAttribute(k_hgemm<256>, cudaFuncAttributeMaxDynamicSharedMemorySize, SMEMH256);
        cudaFuncSetAttribute(k_hgemm<128>, cudaFuncAttributeMaxDynamicSharedMemorySize, SMEMH128);
        cudaStreamCreateWithFlags(&s2, cudaStreamNonBlocking);
        cudaEventCreateWithFlags(&ev_fork, cudaEventDisableTiming);
        cudaEventCreateWithFlags(&ev_cvtT, cudaEventDisableTiming);
        cudaEventCreateWithFlags(&ev_wtf,  cudaEventDisableTiming);
        inited = 1;
    }

    float *ph;
    bf16 *xh, *xl, *lwh, *lwl;
    __half *x16, *a16, *f16b, *wtf, *qw16, *ow16, *fw16, *pw16;
    cudaGetSymbolAddress((void**)&ph,   g_h);
    cudaGetSymbolAddress((void**)&xh,   g_xh);   cudaGetSymbolAddress((void**)&xl,   g_xl);
    cudaGetSymbolAddress((void**)&lwh,  g_lwh);  cudaGetSymbolAddress((void**)&lwl,  g_lwl);
    cudaGetSymbolAddress((void**)&x16,  g_x16);  cudaGetSymbolAddress((void**)&a16,  g_a16);
    cudaGetSymbolAddress((void**)&f16b, g_f16);  cudaGetSymbolAddress((void**)&wtf,  g_wtf);
    cudaGetSymbolAddress((void**)&qw16, g_qw16); cudaGetSymbolAddress((void**)&ow16, g_ow16);
    cudaGetSymbolAddress((void**)&fw16, g_fw16); cudaGetSymbolAddress((void**)&pw16, g_pw16);

    // ---- fork: side stream does weight conversions ----
    cudaEventRecord(ev_fork, 0);
    cudaStreamWaitEvent(s2, ev_fork, 0);
    k_cvtT_all<<<13824, dim3(32,8), 0, s2>>>(wqkv, wo, wfc, wpr);
    cudaEventRecord(ev_cvtT, s2);
    k_cvt_f16<<<(NVP*DM+255)/256, 256, 0, s2>>>(wte, wtf, NVOC*DM, NVP*DM);
    cudaEventRecord(ev_wtf, s2);

    // ---- main: ll weights + embedding + ll GEMM ----
    k_cvt<<<(DM*DM+255)/256, 256>>>(llw, lwh, lwl, DM*DM, DM*DM);
    k_embed<<<MT, 192>>>(wte, ctx, qry, rsp, c2, cl, ql, rl, c2l);

    // h = emb @ ll_w^T + ll_b + wpe  (bf16x3)
    k_tgemm<128><<<dim3(MT/128, DM/128), 256, SMEM128>>>(xh, xl, lwh, lwl, llb, wpe,
                                                         ph, DM, DM, GF_WPE);

    // join: layer weights ready
    cudaStreamWaitEvent(0, ev_cvtT, 0);

    for (int l = 0; l < NLAY; l++) {
        k_ln_f16<<<MT, 256>>>(ph, ln1g + l*DM, ln1b + l*DM, x16);
        k_hgemm<256><<<dim3(MT/128, 3*DM/256), 512, SMEMH256>>>(x16,
            qw16 + (size_t)l*3*DM*DM, bqkv + l*3*DM,
            nullptr, nullptr, DM, 3*DM, GF_QKV);
        k_flash<<<dim3(SL/128, BATCH*NH), 256>>>(cl, c2l, ql, rl);
        k_hgemm<128><<<dim3(MT/128, DM/128), 512, SMEMH128>>>(a16,
            ow16 + (size_t)l*DM*DM, bo + l*DM,
            ph, nullptr, DM, DM, GF_RESID);
        k_ln_f16<<<MT, 256>>>(ph, ln2g + l*DM, ln2b + l*DM, x16);
        k_hgemm<256><<<dim3(MT/128, FF/256), 512, SMEMH256>>>(x16,
            fw16 + (size_t)l*FF*DM, bfc + l*FF,
            nullptr, f16b, DM, FF, GF_GELU);
        k_hgemm<128><<<dim3(MT/128, DM/128), 512, SMEMH128>>>(f16b,
            pw16 + (size_t)l*DM*FF, bpr + l*DM,
            ph, nullptr, FF, DM, GF_RESID);
    }

    k_ln_f16<<<MT, 256>>>(ph, lnfg, lnfb, x16);

    // join: wte fp16 ready for LM head
    cudaStreamWaitEvent(0, ev_wtf, 0);

    // logits = x @ wte^T (fp16 single-pass)
    k_hgemm<256><<<dim3(MT/128, NVP/256), 512, SMEMH256>>>(x16, wtf, nullptr,
                                                           out, nullptr, DM, NVOC, 0);
}